// round 9
// baseline (speedup 1.0000x reference)
#include <cuda_runtime.h>
#include <stdint.h>

// ---------------------------------------------------------------------------
// GPRNet: out = sum_k temp[k] * A_hat^k (MLP(x)@W_fc) + b_fc  (scalar per node)
// CSC counting sort (hist/scan/scatter), then persistent hop kernel:
// 2 blocks x 1024 thr per SM (64 warps/SM = HW max), IVALL grid barrier.
// R9: hop gathers run as FOUR independent 8-lane streams per warp (4x MLP,
// 3-shfl reduce) + final shfl permutation for coalesced writes; k_scan2
// folded into k_scan3.
// ---------------------------------------------------------------------------

#define MAXN   100352
#define MAXE   3276800
#define NBLK   256
#define EBLK   256
#define SCANB  1024
#define MAXSB  128
#define PTHR   1024

__device__ int      g_deg[MAXN];
__device__ int      g_off[MAXN + 1];
__device__ int      g_cursor[MAXN];
__device__ int      g_blk[MAXSB];
__device__ int      g_srow[MAXE];
__device__ float    g_dinv[MAXN];
__device__ float    g_s[MAXN];
__device__ float    g_hidden[MAXN];
__device__ float    g_curwA[MAXN];
__device__ float    g_curwB[MAXN];
__device__ unsigned g_barrier;

// ---- per-node MLP (+ zero histogram, + barrier reset) -----------------------
__global__ void __launch_bounds__(NBLK) k_mlp(
    const float* __restrict__ x,
    const float* __restrict__ W1, const float* __restrict__ b1,
    const float* __restrict__ W2, const float* __restrict__ b2,
    const float* __restrict__ Wfc, int N)
{
    __shared__ float sW1[32], sB1[32], sB2[64], sWfc[64];
    __shared__ __align__(16) float sW2[2048];

    for (int t = threadIdx.x; t < 2048; t += blockDim.x) sW2[t] = W2[t];
    if (threadIdx.x < 32) { sW1[threadIdx.x] = W1[threadIdx.x]; sB1[threadIdx.x] = b1[threadIdx.x]; }
    if (threadIdx.x < 64) { sB2[threadIdx.x] = b2[threadIdx.x]; sWfc[threadIdx.x] = Wfc[threadIdx.x]; }
    __syncthreads();

    int i = blockIdx.x * blockDim.x + threadIdx.x;
    if (i >= N) return;
    if (i == 0) g_barrier = 0;          // reset persistent-kernel barrier

    float xv = x[i];
    float acc[64];
#pragma unroll
    for (int j = 0; j < 64; j++) acc[j] = sB2[j];
#pragma unroll
    for (int j1 = 0; j1 < 32; j1++) {
        float h = fmaxf(fmaf(xv, sW1[j1], sB1[j1]), 0.0f);
        const float4* w2r = reinterpret_cast<const float4*>(&sW2[j1 * 64]);
#pragma unroll
        for (int j = 0; j < 16; j++) {
            float4 w = w2r[j];
            acc[4*j+0] = fmaf(h, w.x, acc[4*j+0]);
            acc[4*j+1] = fmaf(h, w.y, acc[4*j+1]);
            acc[4*j+2] = fmaf(h, w.z, acc[4*j+2]);
            acc[4*j+3] = fmaf(h, w.w, acc[4*j+3]);
        }
    }
    float s = 0.0f;
#pragma unroll
    for (int j = 0; j < 64; j++) s = fmaf(fmaxf(acc[j], 0.0f), sWfc[j], s);

    g_s[i]   = s;
    g_deg[i] = 0;
}

// ---- histogram of col --------------------------------------------------------
__global__ void __launch_bounds__(EBLK) k_hist_vec(const int* __restrict__ col, int E4, int rem)
{
    int t = blockIdx.x * blockDim.x + threadIdx.x;
    if (t < E4) {
        int4 c4 = reinterpret_cast<const int4*>(col)[t];
        atomicAdd(&g_deg[c4.x], 1);
        atomicAdd(&g_deg[c4.y], 1);
        atomicAdd(&g_deg[c4.z], 1);
        atomicAdd(&g_deg[c4.w], 1);
    } else if (t - E4 < rem) {
        atomicAdd(&g_deg[col[4 * E4 + (t - E4)]], 1);
    }
}
__global__ void __launch_bounds__(EBLK) k_hist_sca(const int* __restrict__ col, int E)
{
    int e = blockIdx.x * blockDim.x + threadIdx.x;
    if (e < E) atomicAdd(&g_deg[col[e]], 1);
}

// ---- scan kernel 1: per-block local scan ------------------------------------
__global__ void __launch_bounds__(SCANB) k_scan1(int N)
{
    __shared__ int sh[SCANB];
    int i = blockIdx.x * SCANB + threadIdx.x;
    int v = (i < N) ? g_deg[i] : 0;
    sh[threadIdx.x] = v;
    __syncthreads();
#pragma unroll
    for (int d = 1; d < SCANB; d <<= 1) {
        int t = (threadIdx.x >= d) ? sh[threadIdx.x - d] : 0;
        __syncthreads();
        sh[threadIdx.x] += t;
        __syncthreads();
    }
    int incl = sh[threadIdx.x];
    if (i < N) g_off[i] = incl - v;
    if (threadIdx.x == SCANB - 1) g_blk[blockIdx.x] = incl;
}

// ---- scan kernel 2 (folds old scan2+scan3): block prefix + finalize ----------
__global__ void __launch_bounds__(SCANB) k_scan3(const float* __restrict__ temp, int N, int E)
{
    __shared__ int sPrefix;
    int t = threadIdx.x;
    if (t < 32) {
        int acc = 0;
        for (int j = t; j < blockIdx.x; j += 32) acc += g_blk[j];
#pragma unroll
        for (int d = 16; d > 0; d >>= 1) acc += __shfl_xor_sync(0xFFFFFFFFu, acc, d);
        if (t == 0) sPrefix = acc;
    }
    __syncthreads();

    int i = blockIdx.x * SCANB + t;
    if (i >= N) return;
    int val = g_off[i] + sPrefix;
    g_off[i]    = val;
    g_cursor[i] = val;
    if (i == 0) g_off[N] = E;

    float d = rsqrtf((float)(g_deg[i] + 1));   // +1 self-loop
    g_dinv[i]   = d;
    float s     = g_s[i];
    g_hidden[i] = temp[0] * s;
    g_curwA[i]  = d * s;
}

// ---- scatter edges into CSC order -------------------------------------------
__global__ void __launch_bounds__(EBLK) k_scatter_vec(const int* __restrict__ row,
                                                      const int* __restrict__ col,
                                                      int E4, int rem)
{
    int t = blockIdx.x * blockDim.x + threadIdx.x;
    if (t < E4) {
        int4 r4 = reinterpret_cast<const int4*>(row)[t];
        int4 c4 = reinterpret_cast<const int4*>(col)[t];
        g_srow[atomicAdd(&g_cursor[c4.x], 1)] = r4.x;
        g_srow[atomicAdd(&g_cursor[c4.y], 1)] = r4.y;
        g_srow[atomicAdd(&g_cursor[c4.z], 1)] = r4.z;
        g_srow[atomicAdd(&g_cursor[c4.w], 1)] = r4.w;
    } else if (t - E4 < rem) {
        int e = 4 * E4 + (t - E4);
        g_srow[atomicAdd(&g_cursor[col[e]], 1)] = row[e];
    }
}
__global__ void __launch_bounds__(EBLK) k_scatter_sca(const int* __restrict__ row,
                                                      const int* __restrict__ col, int E)
{
    int e = blockIdx.x * blockDim.x + threadIdx.x;
    if (e < E) g_srow[atomicAdd(&g_cursor[col[e]], 1)] = row[e];
}

// ---- persistent propagation: all K hops, software grid barrier ---------------
// 2 blocks/SM (reg-capped) -> 64 warps/SM. Each warp runs FOUR independent
// 8-lane gather streams (one node per group per round) for 4x per-warp MLP.
__global__ void __launch_bounds__(PTHR, 2) k_prop(const float* __restrict__ temp,
                                                  const float* __restrict__ bfc,
                                                  float* __restrict__ out,
                                                  int N, int K)
{
    const int warpsPerBlk = PTHR / 32;
    const int nwarps = gridDim.x * warpsPerBlk;
    const int gw     = blockIdx.x * warpsPerBlk + (threadIdx.x >> 5);
    const int lane   = threadIdx.x & 31;
    const int grp    = lane >> 3;        // 0..3
    const int lig    = lane & 7;         // lane in 8-lane group

    const int npw    = (N + nwarps - 1) / nwarps;
    const int nodeLo = gw * npw;
    const int nodeHi = (nodeLo + npw < N) ? (nodeLo + npw) : N;

    unsigned target = 0;

    for (int k = 1; k <= K; k++) {
        const float gamma = __ldg(&temp[k]);
        const bool  last  = (k == K);
        const float* curwIn  = (k & 1) ? g_curwA : g_curwB;
        float*       curwOut = (k & 1) ? g_curwB : g_curwA;

        for (int b = nodeLo; b < nodeHi; b += 32) {
            int  cnt = nodeHi - b; if (cnt > 32) cnt = 32;
            int  idx = b + lane;
            bool act = lane < cnt;

            // warp-coalesced node state (1 LDG each)
            int   myStart = act ? __ldg(&g_off[idx])     : 0;
            int   myNext  = act ? __ldg(&g_off[idx + 1]) : 0;
            float myDinv  = act ? g_dinv[idx]            : 0.0f;
            float myHid   = act ? g_hidden[idx]          : 0.0f;
            float mySelf  = act ? curwIn[idx]            : 0.0f;

            // 8 rounds; round j: group g processes node j*4+g (4 streams)
            float held = 0.0f;
#pragma unroll
            for (int j = 0; j < 8; j++) {
                int nIdx = (j << 2) | grp;
                int s = __shfl_sync(0xFFFFFFFFu, myStart, nIdx);
                int e = __shfl_sync(0xFFFFFFFFu, myNext,  nIdx);

                float sum = 0.0f;
                for (int t = s + lig; t < e; t += 8)
                    sum += __ldg(&curwIn[__ldg(&g_srow[t])]);   // L1-cached gather

                sum += __shfl_xor_sync(0xFFFFFFFFu, sum, 4);
                sum += __shfl_xor_sync(0xFFFFFFFFu, sum, 2);
                sum += __shfl_xor_sync(0xFFFFFFFFu, sum, 1);
                if (lig == j) held = sum;
            }
            // node n's sum is held by lane (n&3)*8 + (n>>2); permute so lane P owns node P
            float mySum = __shfl_sync(0xFFFFFFFFu, held, ((lane & 3) << 3) | (lane >> 2));

            float cur = myDinv * (mySelf + mySum);
            float h   = fmaf(gamma, cur, myHid);
            if (act) {
                if (last) {
                    out[idx] = h + __ldg(&bfc[0]);      // coalesced
                } else {
                    g_hidden[idx] = h;                  // coalesced
                    curwOut[idx]  = myDinv * cur;       // coalesced
                }
            }
        }

        if (!last) {
            // grid barrier; gpu-scope fences emit CCTL.IVALL -> L1D coherent
            __syncthreads();
            if (threadIdx.x == 0) {
                __threadfence();                         // release (+IVALL)
                atomicAdd(&g_barrier, 1u);
                target += gridDim.x;
                while (*(volatile unsigned*)&g_barrier < target)
                    __nanosleep(32);
                __threadfence();                         // acquire (+IVALL)
            }
            __syncthreads();
        }
    }
}

// ---------------------------------------------------------------------------
extern "C" void kernel_launch(void* const* d_in, const int* in_sizes, int n_in,
                              void* d_out, int out_size)
{
    const float* x    = (const float*)d_in[0];
    const int*   ei   = (const int*)  d_in[1];
    const float* W1   = (const float*)d_in[2];
    const float* b1   = (const float*)d_in[3];
    const float* W2   = (const float*)d_in[4];
    const float* b2   = (const float*)d_in[5];
    const float* temp = (const float*)d_in[6];
    const float* Wfc  = (const float*)d_in[7];
    const float* bfc  = (const float*)d_in[8];
    float*       out  = (float*)d_out;

    int N = in_sizes[0];
    int E = in_sizes[1] / 2;
    int K = in_sizes[6] - 1;

    const int* row = ei;
    const int* col = ei + E;

    int nb    = (N + NBLK - 1) / NBLK;
    int nscan = (N + SCANB - 1) / SCANB;

    bool vec_ok = (E % 4 == 0);
    int  E4 = E >> 2, rem = E & 3;
    int  eb_vec = (E4 + rem + EBLK - 1) / EBLK;
    int  eb_sca = (E + EBLK - 1) / EBLK;

    // 2 blocks per SM (reg-capped) -> 64 warps/SM, fully co-resident
    int dev = 0, sms = 0;
    cudaGetDevice(&dev);
    cudaDeviceGetAttribute(&sms, cudaDevAttrMultiProcessorCount, dev);
    if (sms <= 0) sms = 148;

    k_mlp<<<nb, NBLK>>>(x, W1, b1, W2, b2, Wfc, N);

    if (vec_ok) k_hist_vec<<<eb_vec, EBLK>>>(col, E4, rem);
    else        k_hist_sca<<<eb_sca, EBLK>>>(col, E);
    k_scan1<<<nscan, SCANB>>>(N);
    k_scan3<<<nscan, SCANB>>>(temp, N, E);
    if (vec_ok) k_scatter_vec<<<eb_vec, EBLK>>>(row, col, E4, rem);
    else        k_scatter_sca<<<eb_sca, EBLK>>>(row, col, E);

    k_prop<<<2 * sms, PTHR>>>(temp, bfc, out, N, K);
}

// round 10
// speedup vs baseline: 1.4759x; 1.4759x over previous
#include <cuda_runtime.h>
#include <stdint.h>

// ---------------------------------------------------------------------------
// GPRNet: out = sum_k temp[k] * A_hat^k (MLP(x)@W_fc) + b_fc  (scalar per node)
// CSC counting sort (hist/scan/scatter), then persistent hop kernel:
// 2 blocks x 1024 thr per SM (64 warps/SM = HW max), IVALL grid barrier.
// R10: hop processes nodes in PAIRS — two independent full-32-lane gather
// chains issued back-to-back (2x per-warp MLP, no divergence narrowing;
// R9's 8-lane scheme is reverted), reductions interleaved.
// ---------------------------------------------------------------------------

#define MAXN   100352
#define MAXE   3276800
#define NBLK   256
#define EBLK   256
#define SCANB  1024
#define MAXSB  128
#define PTHR   1024

__device__ int      g_deg[MAXN];
__device__ int      g_off[MAXN + 1];
__device__ int      g_cursor[MAXN];
__device__ int      g_blk[MAXSB];
__device__ int      g_srow[MAXE];
__device__ float    g_dinv[MAXN];
__device__ float    g_s[MAXN];
__device__ float    g_hidden[MAXN];
__device__ float    g_curwA[MAXN];
__device__ float    g_curwB[MAXN];
__device__ unsigned g_barrier;

// ---- per-node MLP (+ zero histogram, + barrier reset) -----------------------
__global__ void __launch_bounds__(NBLK) k_mlp(
    const float* __restrict__ x,
    const float* __restrict__ W1, const float* __restrict__ b1,
    const float* __restrict__ W2, const float* __restrict__ b2,
    const float* __restrict__ Wfc, int N)
{
    __shared__ float sW1[32], sB1[32], sB2[64], sWfc[64];
    __shared__ __align__(16) float sW2[2048];

    for (int t = threadIdx.x; t < 2048; t += blockDim.x) sW2[t] = W2[t];
    if (threadIdx.x < 32) { sW1[threadIdx.x] = W1[threadIdx.x]; sB1[threadIdx.x] = b1[threadIdx.x]; }
    if (threadIdx.x < 64) { sB2[threadIdx.x] = b2[threadIdx.x]; sWfc[threadIdx.x] = Wfc[threadIdx.x]; }
    __syncthreads();

    int i = blockIdx.x * blockDim.x + threadIdx.x;
    if (i >= N) return;
    if (i == 0) g_barrier = 0;          // reset persistent-kernel barrier

    float xv = x[i];
    float acc[64];
#pragma unroll
    for (int j = 0; j < 64; j++) acc[j] = sB2[j];
#pragma unroll
    for (int j1 = 0; j1 < 32; j1++) {
        float h = fmaxf(fmaf(xv, sW1[j1], sB1[j1]), 0.0f);
        const float4* w2r = reinterpret_cast<const float4*>(&sW2[j1 * 64]);
#pragma unroll
        for (int j = 0; j < 16; j++) {
            float4 w = w2r[j];
            acc[4*j+0] = fmaf(h, w.x, acc[4*j+0]);
            acc[4*j+1] = fmaf(h, w.y, acc[4*j+1]);
            acc[4*j+2] = fmaf(h, w.z, acc[4*j+2]);
            acc[4*j+3] = fmaf(h, w.w, acc[4*j+3]);
        }
    }
    float s = 0.0f;
#pragma unroll
    for (int j = 0; j < 64; j++) s = fmaf(fmaxf(acc[j], 0.0f), sWfc[j], s);

    g_s[i]   = s;
    g_deg[i] = 0;
}

// ---- histogram of col --------------------------------------------------------
__global__ void __launch_bounds__(EBLK) k_hist_vec(const int* __restrict__ col, int E4, int rem)
{
    int t = blockIdx.x * blockDim.x + threadIdx.x;
    if (t < E4) {
        int4 c4 = reinterpret_cast<const int4*>(col)[t];
        atomicAdd(&g_deg[c4.x], 1);
        atomicAdd(&g_deg[c4.y], 1);
        atomicAdd(&g_deg[c4.z], 1);
        atomicAdd(&g_deg[c4.w], 1);
    } else if (t - E4 < rem) {
        atomicAdd(&g_deg[col[4 * E4 + (t - E4)]], 1);
    }
}
__global__ void __launch_bounds__(EBLK) k_hist_sca(const int* __restrict__ col, int E)
{
    int e = blockIdx.x * blockDim.x + threadIdx.x;
    if (e < E) atomicAdd(&g_deg[col[e]], 1);
}

// ---- scan kernel 1: per-block local scan ------------------------------------
__global__ void __launch_bounds__(SCANB) k_scan1(int N)
{
    __shared__ int sh[SCANB];
    int i = blockIdx.x * SCANB + threadIdx.x;
    int v = (i < N) ? g_deg[i] : 0;
    sh[threadIdx.x] = v;
    __syncthreads();
#pragma unroll
    for (int d = 1; d < SCANB; d <<= 1) {
        int t = (threadIdx.x >= d) ? sh[threadIdx.x - d] : 0;
        __syncthreads();
        sh[threadIdx.x] += t;
        __syncthreads();
    }
    int incl = sh[threadIdx.x];
    if (i < N) g_off[i] = incl - v;
    if (threadIdx.x == SCANB - 1) g_blk[blockIdx.x] = incl;
}

// ---- scan kernel 2 (folds block prefix + finalize + hop-0 seed) --------------
__global__ void __launch_bounds__(SCANB) k_scan3(const float* __restrict__ temp, int N, int E)
{
    __shared__ int sPrefix;
    int t = threadIdx.x;
    if (t < 32) {
        int acc = 0;
        for (int j = t; j < blockIdx.x; j += 32) acc += g_blk[j];
#pragma unroll
        for (int d = 16; d > 0; d >>= 1) acc += __shfl_xor_sync(0xFFFFFFFFu, acc, d);
        if (t == 0) sPrefix = acc;
    }
    __syncthreads();

    int i = blockIdx.x * SCANB + t;
    if (i >= N) return;
    int val = g_off[i] + sPrefix;
    g_off[i]    = val;
    g_cursor[i] = val;
    if (i == 0) g_off[N] = E;

    float d = rsqrtf((float)(g_deg[i] + 1));   // +1 self-loop
    g_dinv[i]   = d;
    float s     = g_s[i];
    g_hidden[i] = temp[0] * s;
    g_curwA[i]  = d * s;
}

// ---- scatter edges into CSC order -------------------------------------------
__global__ void __launch_bounds__(EBLK) k_scatter_vec(const int* __restrict__ row,
                                                      const int* __restrict__ col,
                                                      int E4, int rem)
{
    int t = blockIdx.x * blockDim.x + threadIdx.x;
    if (t < E4) {
        int4 r4 = reinterpret_cast<const int4*>(row)[t];
        int4 c4 = reinterpret_cast<const int4*>(col)[t];
        g_srow[atomicAdd(&g_cursor[c4.x], 1)] = r4.x;
        g_srow[atomicAdd(&g_cursor[c4.y], 1)] = r4.y;
        g_srow[atomicAdd(&g_cursor[c4.z], 1)] = r4.z;
        g_srow[atomicAdd(&g_cursor[c4.w], 1)] = r4.w;
    } else if (t - E4 < rem) {
        int e = 4 * E4 + (t - E4);
        g_srow[atomicAdd(&g_cursor[col[e]], 1)] = row[e];
    }
}
__global__ void __launch_bounds__(EBLK) k_scatter_sca(const int* __restrict__ row,
                                                      const int* __restrict__ col, int E)
{
    int e = blockIdx.x * blockDim.x + threadIdx.x;
    if (e < E) g_srow[atomicAdd(&g_cursor[col[e]], 1)] = row[e];
}

// ---- persistent propagation: all K hops, software grid barrier ---------------
// 2 blocks/SM (reg-capped) -> 64 warps/SM. Nodes processed in PAIRS:
// two independent full-width gather chains in flight per warp.
__global__ void __launch_bounds__(PTHR, 2) k_prop(const float* __restrict__ temp,
                                                  const float* __restrict__ bfc,
                                                  float* __restrict__ out,
                                                  int N, int K)
{
    const int warpsPerBlk = PTHR / 32;
    const int nwarps = gridDim.x * warpsPerBlk;
    const int gw     = blockIdx.x * warpsPerBlk + (threadIdx.x >> 5);
    const int lane   = threadIdx.x & 31;

    const int npw    = (N + nwarps - 1) / nwarps;
    const int nodeLo = gw * npw;
    const int nodeHi = (nodeLo + npw < N) ? (nodeLo + npw) : N;

    unsigned target = 0;

    for (int k = 1; k <= K; k++) {
        const float gamma = __ldg(&temp[k]);
        const bool  last  = (k == K);
        const float* curwIn  = (k & 1) ? g_curwA : g_curwB;
        float*       curwOut = (k & 1) ? g_curwB : g_curwA;

        for (int b = nodeLo; b < nodeHi; b += 32) {
            int  cnt = nodeHi - b; if (cnt > 32) cnt = 32;
            int  idx = b + lane;
            bool act = lane < cnt;

            // warp-coalesced node state (1 LDG each)
            int   myStart = act ? __ldg(&g_off[idx])     : 0;
            int   myNext  = act ? __ldg(&g_off[idx + 1]) : 0;
            float myDinv  = act ? g_dinv[idx]            : 0.0f;
            float myHid   = act ? g_hidden[idx]          : 0.0f;
            float mySelf  = act ? curwIn[idx]            : 0.0f;
            float mySum   = 0.0f;

            // pairs of nodes: two independent full-width gather chains
            for (int j = 0; j < cnt; j += 2) {
                int s0 = __shfl_sync(0xFFFFFFFFu, myStart, j);
                int e0 = __shfl_sync(0xFFFFFFFFu, myNext,  j);
                int j1 = (j + 1 < cnt) ? (j + 1) : j;      // safe source
                int s1 = __shfl_sync(0xFFFFFFFFu, myStart, j1);
                int e1 = __shfl_sync(0xFFFFFFFFu, myNext,  j1);
                if (j + 1 >= cnt) { s1 = 0; e1 = 0; }      // disable stream 1

                float sum0 = 0.0f, sum1 = 0.0f;
                int   t0 = s0 + lane, t1 = s1 + lane;
                while (t0 < e0 || t1 < e1) {
                    float v0 = 0.0f, v1 = 0.0f;
                    if (t0 < e0) v0 = __ldg(&curwIn[__ldg(&g_srow[t0])]);
                    if (t1 < e1) v1 = __ldg(&curwIn[__ldg(&g_srow[t1])]);
                    sum0 += v0; sum1 += v1;
                    t0 += 32;  t1 += 32;
                }

#pragma unroll
                for (int d = 16; d > 0; d >>= 1) {
                    sum0 += __shfl_xor_sync(0xFFFFFFFFu, sum0, d);
                    sum1 += __shfl_xor_sync(0xFFFFFFFFu, sum1, d);
                }
                if (lane == j)     mySum = sum0;
                if (lane == j + 1) mySum = sum1;
            }

            float cur = myDinv * (mySelf + mySum);
            float h   = fmaf(gamma, cur, myHid);
            if (act) {
                if (last) {
                    out[idx] = h + __ldg(&bfc[0]);      // coalesced
                } else {
                    g_hidden[idx] = h;                  // coalesced
                    curwOut[idx]  = myDinv * cur;       // coalesced
                }
            }
        }

        if (!last) {
            // grid barrier; gpu-scope fences emit CCTL.IVALL -> L1D coherent
            __syncthreads();
            if (threadIdx.x == 0) {
                __threadfence();                         // release (+IVALL)
                atomicAdd(&g_barrier, 1u);
                target += gridDim.x;
                while (*(volatile unsigned*)&g_barrier < target)
                    __nanosleep(32);
                __threadfence();                         // acquire (+IVALL)
            }
            __syncthreads();
        }
    }
}

// ---------------------------------------------------------------------------
extern "C" void kernel_launch(void* const* d_in, const int* in_sizes, int n_in,
                              void* d_out, int out_size)
{
    const float* x    = (const float*)d_in[0];
    const int*   ei   = (const int*)  d_in[1];
    const float* W1   = (const float*)d_in[2];
    const float* b1   = (const float*)d_in[3];
    const float* W2   = (const float*)d_in[4];
    const float* b2   = (const float*)d_in[5];
    const float* temp = (const float*)d_in[6];
    const float* Wfc  = (const float*)d_in[7];
    const float* bfc  = (const float*)d_in[8];
    float*       out  = (float*)d_out;

    int N = in_sizes[0];
    int E = in_sizes[1] / 2;
    int K = in_sizes[6] - 1;

    const int* row = ei;
    const int* col = ei + E;

    int nb    = (N + NBLK - 1) / NBLK;
    int nscan = (N + SCANB - 1) / SCANB;

    bool vec_ok = (E % 4 == 0);
    int  E4 = E >> 2, rem = E & 3;
    int  eb_vec = (E4 + rem + EBLK - 1) / EBLK;
    int  eb_sca = (E + EBLK - 1) / EBLK;

    // 2 blocks per SM (reg-capped) -> 64 warps/SM, fully co-resident
    int dev = 0, sms = 0;
    cudaGetDevice(&dev);
    cudaDeviceGetAttribute(&sms, cudaDevAttrMultiProcessorCount, dev);
    if (sms <= 0) sms = 148;

    k_mlp<<<nb, NBLK>>>(x, W1, b1, W2, b2, Wfc, N);

    if (vec_ok) k_hist_vec<<<eb_vec, EBLK>>>(col, E4, rem);
    else        k_hist_sca<<<eb_sca, EBLK>>>(col, E);
    k_scan1<<<nscan, SCANB>>>(N);
    k_scan3<<<nscan, SCANB>>>(temp, N, E);
    if (vec_ok) k_scatter_vec<<<eb_vec, EBLK>>>(row, col, E4, rem);
    else        k_scatter_sca<<<eb_sca, EBLK>>>(row, col, E);

    k_prop<<<2 * sms, PTHR>>>(temp, bfc, out, N, K);
}

// round 11
// speedup vs baseline: 1.7639x; 1.1952x over previous
#include <cuda_runtime.h>
#include <cuda_fp16.h>
#include <stdint.h>

// ---------------------------------------------------------------------------
// GPRNet: out = sum_k temp[k] * A_hat^k (MLP(x)@W_fc) + b_fc  (scalar per node)
// CSC counting sort (hist/scan/scatter, fp32), then persistent hop kernel:
// 1 block/SM x 1024 thr, 196KB dynamic smem holding the ENTIRE curw vector as
// fp16. Per hop: bulk-fill smem from a double-buffered global fp16 array,
// gather neighbors from smem (LDS ~4cyc/warp vs ~30 wavefront-cyc for random
// LDG -> breaks the L1tex wavefront floor), node state held in REGISTERS
// across all hops (each warp owns <=32 nodes). IVALL grid barrier between
// hops (validated R6+).
// Precision: neighbor terms fp16 (~1.5e-4), self/hidden fp32.
// ---------------------------------------------------------------------------

#define MAXN   100352
#define MAXE   3276800
#define NBLK   256
#define EBLK   256
#define SCANB  1024
#define MAXSB  128
#define PTHR   1024
#define SMEMB  (MAXN * 2)          // 200704 bytes of fp16 curw
#define NH4    (SMEMB / 16)        // 12544 uint4s

__device__ int      g_deg[MAXN];
__device__ int      g_off[MAXN + 1];
__device__ int      g_cursor[MAXN];
__device__ int      g_blk[MAXSB];
__device__ int      g_srow[MAXE];
__device__ float    g_dinv[MAXN];
__device__ float    g_s[MAXN];
__device__ float    g_hidden[MAXN];
__device__ float    g_curwA[MAXN];                       // fp32 seed (self terms)
__device__ __align__(16) __half g_hA[MAXN];              // fp16 ping
__device__ __align__(16) __half g_hB[MAXN];              // fp16 pong
__device__ unsigned g_barrier;

// ---- per-node MLP (+ zero histogram, + barrier reset) -----------------------
__global__ void __launch_bounds__(NBLK) k_mlp(
    const float* __restrict__ x,
    const float* __restrict__ W1, const float* __restrict__ b1,
    const float* __restrict__ W2, const float* __restrict__ b2,
    const float* __restrict__ Wfc, int N)
{
    __shared__ float sW1[32], sB1[32], sB2[64], sWfc[64];
    __shared__ __align__(16) float sW2[2048];

    for (int t = threadIdx.x; t < 2048; t += blockDim.x) sW2[t] = W2[t];
    if (threadIdx.x < 32) { sW1[threadIdx.x] = W1[threadIdx.x]; sB1[threadIdx.x] = b1[threadIdx.x]; }
    if (threadIdx.x < 64) { sB2[threadIdx.x] = b2[threadIdx.x]; sWfc[threadIdx.x] = Wfc[threadIdx.x]; }
    __syncthreads();

    int i = blockIdx.x * blockDim.x + threadIdx.x;
    if (i >= N) return;
    if (i == 0) g_barrier = 0;          // reset persistent-kernel barrier

    float xv = x[i];
    float acc[64];
#pragma unroll
    for (int j = 0; j < 64; j++) acc[j] = sB2[j];
#pragma unroll
    for (int j1 = 0; j1 < 32; j1++) {
        float h = fmaxf(fmaf(xv, sW1[j1], sB1[j1]), 0.0f);
        const float4* w2r = reinterpret_cast<const float4*>(&sW2[j1 * 64]);
#pragma unroll
        for (int j = 0; j < 16; j++) {
            float4 w = w2r[j];
            acc[4*j+0] = fmaf(h, w.x, acc[4*j+0]);
            acc[4*j+1] = fmaf(h, w.y, acc[4*j+1]);
            acc[4*j+2] = fmaf(h, w.z, acc[4*j+2]);
            acc[4*j+3] = fmaf(h, w.w, acc[4*j+3]);
        }
    }
    float s = 0.0f;
#pragma unroll
    for (int j = 0; j < 64; j++) s = fmaf(fmaxf(acc[j], 0.0f), sWfc[j], s);

    g_s[i]   = s;
    g_deg[i] = 0;
}

// ---- histogram of col --------------------------------------------------------
__global__ void __launch_bounds__(EBLK) k_hist_vec(const int* __restrict__ col, int E4, int rem)
{
    int t = blockIdx.x * blockDim.x + threadIdx.x;
    if (t < E4) {
        int4 c4 = reinterpret_cast<const int4*>(col)[t];
        atomicAdd(&g_deg[c4.x], 1);
        atomicAdd(&g_deg[c4.y], 1);
        atomicAdd(&g_deg[c4.z], 1);
        atomicAdd(&g_deg[c4.w], 1);
    } else if (t - E4 < rem) {
        atomicAdd(&g_deg[col[4 * E4 + (t - E4)]], 1);
    }
}
__global__ void __launch_bounds__(EBLK) k_hist_sca(const int* __restrict__ col, int E)
{
    int e = blockIdx.x * blockDim.x + threadIdx.x;
    if (e < E) atomicAdd(&g_deg[col[e]], 1);
}

// ---- scan kernel 1: per-block local scan ------------------------------------
__global__ void __launch_bounds__(SCANB) k_scan1(int N)
{
    __shared__ int sh[SCANB];
    int i = blockIdx.x * SCANB + threadIdx.x;
    int v = (i < N) ? g_deg[i] : 0;
    sh[threadIdx.x] = v;
    __syncthreads();
#pragma unroll
    for (int d = 1; d < SCANB; d <<= 1) {
        int t = (threadIdx.x >= d) ? sh[threadIdx.x - d] : 0;
        __syncthreads();
        sh[threadIdx.x] += t;
        __syncthreads();
    }
    int incl = sh[threadIdx.x];
    if (i < N) g_off[i] = incl - v;
    if (threadIdx.x == SCANB - 1) g_blk[blockIdx.x] = incl;
}

// ---- scan kernel 2: block prefix + finalize + hop-0 seed ---------------------
__global__ void __launch_bounds__(SCANB) k_scan3(const float* __restrict__ temp, int N, int E)
{
    __shared__ int sPrefix;
    int t = threadIdx.x;
    if (t < 32) {
        int acc = 0;
        for (int j = t; j < blockIdx.x; j += 32) acc += g_blk[j];
#pragma unroll
        for (int d = 16; d > 0; d >>= 1) acc += __shfl_xor_sync(0xFFFFFFFFu, acc, d);
        if (t == 0) sPrefix = acc;
    }
    __syncthreads();

    int i = blockIdx.x * SCANB + t;
    if (i >= N) return;
    int val = g_off[i] + sPrefix;
    g_off[i]    = val;
    g_cursor[i] = val;
    if (i == 0) g_off[N] = E;

    float d = rsqrtf((float)(g_deg[i] + 1));   // +1 self-loop
    float s = g_s[i];
    float w = d * s;
    g_dinv[i]   = d;
    g_hidden[i] = temp[0] * s;
    g_curwA[i]  = w;                    // fp32 self-term seed
    g_hA[i]     = __float2half(w);      // fp16 gather seed (hop 1 reads hA)
}

// ---- scatter edges into CSC order -------------------------------------------
__global__ void __launch_bounds__(EBLK) k_scatter_vec(const int* __restrict__ row,
                                                      const int* __restrict__ col,
                                                      int E4, int rem)
{
    int t = blockIdx.x * blockDim.x + threadIdx.x;
    if (t < E4) {
        int4 r4 = reinterpret_cast<const int4*>(row)[t];
        int4 c4 = reinterpret_cast<const int4*>(col)[t];
        g_srow[atomicAdd(&g_cursor[c4.x], 1)] = r4.x;
        g_srow[atomicAdd(&g_cursor[c4.y], 1)] = r4.y;
        g_srow[atomicAdd(&g_cursor[c4.z], 1)] = r4.z;
        g_srow[atomicAdd(&g_cursor[c4.w], 1)] = r4.w;
    } else if (t - E4 < rem) {
        int e = 4 * E4 + (t - E4);
        g_srow[atomicAdd(&g_cursor[col[e]], 1)] = row[e];
    }
}
__global__ void __launch_bounds__(EBLK) k_scatter_sca(const int* __restrict__ row,
                                                      const int* __restrict__ col, int E)
{
    int e = blockIdx.x * blockDim.x + threadIdx.x;
    if (e < E) g_srow[atomicAdd(&g_cursor[col[e]], 1)] = row[e];
}

// ---- persistent propagation: smem-gather hops --------------------------------
// 1 block/SM, 1024 thr, 196KB smem = full fp16 curw. Node state in registers.
__global__ void __launch_bounds__(PTHR, 1) k_prop(const float* __restrict__ temp,
                                                  const float* __restrict__ bfc,
                                                  float* __restrict__ out,
                                                  int N, int K)
{
    extern __shared__ __align__(16) unsigned char smem_raw[];
    __half* sm   = reinterpret_cast<__half*>(smem_raw);
    uint4*  sm4  = reinterpret_cast<uint4*>(smem_raw);

    const int tid    = threadIdx.x;
    const int nwarps = gridDim.x * (PTHR / 32);
    const int gw     = blockIdx.x * (PTHR / 32) + (tid >> 5);
    const int lane   = tid & 31;

    // each warp owns a contiguous chunk of <=32 nodes; lane -> node (registers!)
    const int npw    = (N + nwarps - 1) / nwarps;          // 21 for this shape
    const int nodeLo = gw * npw;
    const int nodeHi = (nodeLo + npw < N) ? (nodeLo + npw) : N;
    const int cnt    = (nodeHi > nodeLo) ? (nodeHi - nodeLo) : 0;
    const int idx    = nodeLo + lane;
    const bool act   = (lane < cnt);

    int   myStart = act ? __ldg(&g_off[idx])     : 0;
    int   myNext  = act ? __ldg(&g_off[idx + 1]) : 0;
    float myDinv  = act ? g_dinv[idx]            : 0.0f;
    float myHid   = act ? g_hidden[idx]          : 0.0f;
    float mySelf  = act ? g_curwA[idx]           : 0.0f;

    unsigned target = 0;

    for (int k = 1; k <= K; k++) {
        const float gamma = __ldg(&temp[k]);
        const bool  last  = (k == K);
        const uint4* src4 = reinterpret_cast<const uint4*>((k & 1) ? g_hA : g_hB);
        __half*      dstH = (k & 1) ? g_hB : g_hA;

        // fill smem with full fp16 curw (bulk, coalesced)
#pragma unroll 4
        for (int i = tid; i < NH4; i += PTHR)
            sm4[i] = __ldg(&src4[i]);
        __syncthreads();

        // paired full-width smem gathers
        float mySum = 0.0f;
        for (int j = 0; j < cnt; j += 2) {
            int s0 = __shfl_sync(0xFFFFFFFFu, myStart, j);
            int e0 = __shfl_sync(0xFFFFFFFFu, myNext,  j);
            int j1 = (j + 1 < cnt) ? (j + 1) : j;
            int s1 = __shfl_sync(0xFFFFFFFFu, myStart, j1);
            int e1 = __shfl_sync(0xFFFFFFFFu, myNext,  j1);
            if (j + 1 >= cnt) { s1 = 0; e1 = 0; }

            float sum0 = 0.0f, sum1 = 0.0f;
            int   t0 = s0 + lane, t1 = s1 + lane;
            while (t0 < e0 || t1 < e1) {
                float v0 = 0.0f, v1 = 0.0f;
                if (t0 < e0) v0 = __half2float(sm[__ldg(&g_srow[t0])]);
                if (t1 < e1) v1 = __half2float(sm[__ldg(&g_srow[t1])]);
                sum0 += v0; sum1 += v1;
                t0 += 32;  t1 += 32;
            }
#pragma unroll
            for (int d = 16; d > 0; d >>= 1) {
                sum0 += __shfl_xor_sync(0xFFFFFFFFu, sum0, d);
                sum1 += __shfl_xor_sync(0xFFFFFFFFu, sum1, d);
            }
            if (lane == j)     mySum = sum0;
            if (lane == j + 1) mySum = sum1;
        }

        float cur = myDinv * (mySelf + mySum);
        myHid  = fmaf(gamma, cur, myHid);
        mySelf = myDinv * cur;

        if (!last) {
            if (act) dstH[idx] = __float2half(mySelf);   // coalesced 2B
            // grid barrier; gpu-scope fences emit CCTL.IVALL -> coherent fills
            __syncthreads();
            if (tid == 0) {
                __threadfence();                          // release (+IVALL)
                atomicAdd(&g_barrier, 1u);
                target += gridDim.x;
                while (*(volatile unsigned*)&g_barrier < target)
                    __nanosleep(32);
                __threadfence();                          // acquire (+IVALL)
            }
            __syncthreads();
        }
    }

    if (act) out[idx] = myHid + __ldg(&bfc[0]);
}

// ---------------------------------------------------------------------------
extern "C" void kernel_launch(void* const* d_in, const int* in_sizes, int n_in,
                              void* d_out, int out_size)
{
    const float* x    = (const float*)d_in[0];
    const int*   ei   = (const int*)  d_in[1];
    const float* W1   = (const float*)d_in[2];
    const float* b1   = (const float*)d_in[3];
    const float* W2   = (const float*)d_in[4];
    const float* b2   = (const float*)d_in[5];
    const float* temp = (const float*)d_in[6];
    const float* Wfc  = (const float*)d_in[7];
    const float* bfc  = (const float*)d_in[8];
    float*       out  = (float*)d_out;

    int N = in_sizes[0];
    int E = in_sizes[1] / 2;
    int K = in_sizes[6] - 1;

    const int* row = ei;
    const int* col = ei + E;

    int nb    = (N + NBLK - 1) / NBLK;
    int nscan = (N + SCANB - 1) / SCANB;

    bool vec_ok = (E % 4 == 0);
    int  E4 = E >> 2, rem = E & 3;
    int  eb_vec = (E4 + rem + EBLK - 1) / EBLK;
    int  eb_sca = (E + EBLK - 1) / EBLK;

    int dev = 0, sms = 0;
    cudaGetDevice(&dev);
    cudaDeviceGetAttribute(&sms, cudaDevAttrMultiProcessorCount, dev);
    if (sms <= 0) sms = 148;

    static int attr_done = 0;
    if (!attr_done) {
        cudaFuncSetAttribute(k_prop, cudaFuncAttributeMaxDynamicSharedMemorySize, SMEMB);
        attr_done = 1;
    }

    k_mlp<<<nb, NBLK>>>(x, W1, b1, W2, b2, Wfc, N);

    if (vec_ok) k_hist_vec<<<eb_vec, EBLK>>>(col, E4, rem);
    else        k_hist_sca<<<eb_sca, EBLK>>>(col, E);
    k_scan1<<<nscan, SCANB>>>(N);
    k_scan3<<<nscan, SCANB>>>(temp, N, E);
    if (vec_ok) k_scatter_vec<<<eb_vec, EBLK>>>(row, col, E4, rem);
    else        k_scatter_sca<<<eb_sca, EBLK>>>(row, col, E);

    k_prop<<<sms, PTHR, SMEMB>>>(temp, bfc, out, N, K);
}

// round 12
// speedup vs baseline: 1.8421x; 1.0443x over previous
#include <cuda_runtime.h>
#include <cuda_fp16.h>
#include <stdint.h>

// ---------------------------------------------------------------------------
// GPRNet: out = sum_k temp[k] * A_hat^k (MLP(x)@W_fc) + b_fc  (scalar per node)
// Pipeline (4 launches):
//   k_mlp_hist : fused per-node MLP (blocks [0,nb)) + col histogram (rest),
//                resets grid barrier + lookback state
//   k_scan     : single-pass decoupled-lookback scan -> CSC offsets, cursor,
//                dinv, hidden, fp32+fp16 hop-0 seeds; zeroes g_deg for next call
//   k_scatter  : CSC counting-sort scatter
//   k_prop     : persistent, 1 block/SM x 1024 thr, 196KB smem = full fp16
//                curw; per hop ONE cp.async.bulk (TMA) fills smem, gathers
//                run from smem, node state in registers, IVALL grid barrier.
// ---------------------------------------------------------------------------

#define MAXN   100352
#define MAXE   3276800
#define NBLK   256
#define EBLK   256
#define SCANB  1024
#define MAXSB  128
#define PTHR   1024
#define SMEMB  (MAXN * 2)          // 200704 bytes of fp16 curw (16B multiple)
#define SMEMT  (SMEMB + 16)        // + mbarrier slot

__device__ int      g_deg[MAXN];           // zero at every call entry (invariant)
__device__ int      g_off[MAXN + 1];
__device__ int      g_cursor[MAXN];
__device__ int      g_srow[MAXE];
__device__ float    g_dinv[MAXN];
__device__ float    g_s[MAXN];
__device__ float    g_hidden[MAXN];
__device__ float    g_curwA[MAXN];                       // fp32 self-term seed
__device__ __align__(16) __half g_hA[MAXN];              // fp16 ping
__device__ __align__(16) __half g_hB[MAXN];              // fp16 pong
__device__ unsigned g_barrier;
__device__ unsigned long long g_lb[MAXSB];               // lookback: flag<<32|val

// ---- fused per-node MLP + histogram -----------------------------------------
__global__ void __launch_bounds__(NBLK) k_mlp_hist(
    const float* __restrict__ x,
    const float* __restrict__ W1, const float* __restrict__ b1,
    const float* __restrict__ W2, const float* __restrict__ b2,
    const float* __restrict__ Wfc,
    const int* __restrict__ col,
    int N, int nbMlp, int E4, int rem)
{
    if ((int)blockIdx.x >= nbMlp) {
        // ---- histogram role ----
        int hb = blockIdx.x - nbMlp;
        if (hb == 0 && threadIdx.x < MAXSB) g_lb[threadIdx.x] = 0ull;  // reset lookback
        int t = hb * NBLK + threadIdx.x;
        if (t < E4) {
            int4 c4 = reinterpret_cast<const int4*>(col)[t];
            atomicAdd(&g_deg[c4.x], 1);
            atomicAdd(&g_deg[c4.y], 1);
            atomicAdd(&g_deg[c4.z], 1);
            atomicAdd(&g_deg[c4.w], 1);
        } else if (t - E4 < rem) {
            atomicAdd(&g_deg[col[4 * E4 + (t - E4)]], 1);
        }
        return;
    }

    // ---- MLP role ----
    __shared__ float sW1[32], sB1[32], sB2[64], sWfc[64];
    __shared__ __align__(16) float sW2[2048];

    for (int t = threadIdx.x; t < 2048; t += blockDim.x) sW2[t] = W2[t];
    if (threadIdx.x < 32) { sW1[threadIdx.x] = W1[threadIdx.x]; sB1[threadIdx.x] = b1[threadIdx.x]; }
    if (threadIdx.x < 64) { sB2[threadIdx.x] = b2[threadIdx.x]; sWfc[threadIdx.x] = Wfc[threadIdx.x]; }
    __syncthreads();

    int i = blockIdx.x * blockDim.x + threadIdx.x;
    if (i >= N) return;
    if (i == 0) g_barrier = 0;          // reset persistent-kernel barrier

    float xv = x[i];
    float acc[64];
#pragma unroll
    for (int j = 0; j < 64; j++) acc[j] = sB2[j];
#pragma unroll
    for (int j1 = 0; j1 < 32; j1++) {
        float h = fmaxf(fmaf(xv, sW1[j1], sB1[j1]), 0.0f);
        const float4* w2r = reinterpret_cast<const float4*>(&sW2[j1 * 64]);
#pragma unroll
        for (int j = 0; j < 16; j++) {
            float4 w = w2r[j];
            acc[4*j+0] = fmaf(h, w.x, acc[4*j+0]);
            acc[4*j+1] = fmaf(h, w.y, acc[4*j+1]);
            acc[4*j+2] = fmaf(h, w.z, acc[4*j+2]);
            acc[4*j+3] = fmaf(h, w.w, acc[4*j+3]);
        }
    }
    float s = 0.0f;
#pragma unroll
    for (int j = 0; j < 64; j++) s = fmaf(fmaxf(acc[j], 0.0f), sWfc[j], s);

    g_s[i] = s;
}

// ---- single-pass decoupled-lookback scan + finalize + hop-0 seed -------------
// <=128 blocks of 1024 thr (all wave-1 resident on 148+ SMs -> spin-safe).
__global__ void __launch_bounds__(SCANB) k_scan(const float* __restrict__ temp, int N, int E)
{
    __shared__ int sh[SCANB];
    __shared__ int sPrefix;
    const int tid = threadIdx.x;
    const int bid = blockIdx.x;
    const int i   = bid * SCANB + tid;

    int v = (i < N) ? g_deg[i] : 0;
    sh[tid] = v;
    __syncthreads();
#pragma unroll
    for (int d = 1; d < SCANB; d <<= 1) {
        int t = (tid >= d) ? sh[tid - d] : 0;
        __syncthreads();
        sh[tid] += t;
        __syncthreads();
    }
    int incl = sh[tid];

    // block aggregate over valid lanes
    int base   = bid * SCANB;
    int nvalid = N - base; if (nvalid > SCANB) nvalid = SCANB; if (nvalid < 0) nvalid = 0;
    if (tid == 0) {
        int agg = nvalid ? sh[nvalid - 1] : 0;
        if (bid == 0) {
            atomicExch(&g_lb[0], (2ull << 32) | (unsigned)agg);   // inclusive prefix
            sPrefix = 0;
        } else {
            atomicExch(&g_lb[bid], (1ull << 32) | (unsigned)agg); // aggregate
            // lookback
            unsigned long long sum = 0;
            int j = bid - 1;
            for (;;) {
                unsigned long long st;
                do { st = atomicAdd(&g_lb[j], 0ull); if (!(st >> 32)) __nanosleep(32); } while (!(st >> 32));
                sum += (unsigned)st;
                if ((st >> 32) == 2ull) break;
                j--;
            }
            atomicExch(&g_lb[bid], (2ull << 32) | (unsigned)(sum + agg));
            sPrefix = (int)sum;
        }
    }
    __syncthreads();

    if (i >= N) return;
    int val = incl - v + sPrefix;       // global exclusive
    g_off[i]    = val;
    g_cursor[i] = val;
    if (i == 0) g_off[N] = E;

    float d = rsqrtf((float)(g_deg[i] + 1));   // +1 self-loop
    g_deg[i] = 0;                               // restore zero-entry invariant
    float s = g_s[i];
    float w = d * s;
    g_dinv[i]   = d;
    g_hidden[i] = temp[0] * s;
    g_curwA[i]  = w;                    // fp32 self-term seed
    g_hA[i]     = __float2half(w);      // fp16 gather seed (hop 1 reads hA)
}

// ---- scatter edges into CSC order -------------------------------------------
__global__ void __launch_bounds__(EBLK) k_scatter_vec(const int* __restrict__ row,
                                                      const int* __restrict__ col,
                                                      int E4, int rem)
{
    int t = blockIdx.x * blockDim.x + threadIdx.x;
    if (t < E4) {
        int4 r4 = reinterpret_cast<const int4*>(row)[t];
        int4 c4 = reinterpret_cast<const int4*>(col)[t];
        g_srow[atomicAdd(&g_cursor[c4.x], 1)] = r4.x;
        g_srow[atomicAdd(&g_cursor[c4.y], 1)] = r4.y;
        g_srow[atomicAdd(&g_cursor[c4.z], 1)] = r4.z;
        g_srow[atomicAdd(&g_cursor[c4.w], 1)] = r4.w;
    } else if (t - E4 < rem) {
        int e = 4 * E4 + (t - E4);
        g_srow[atomicAdd(&g_cursor[col[e]], 1)] = row[e];
    }
}
__global__ void __launch_bounds__(EBLK) k_scatter_sca(const int* __restrict__ row,
                                                      const int* __restrict__ col, int E)
{
    int e = blockIdx.x * blockDim.x + threadIdx.x;
    if (e < E) g_srow[atomicAdd(&g_cursor[col[e]], 1)] = row[e];
}

// ---- persistent propagation: TMA-filled smem-gather hops ---------------------
__global__ void __launch_bounds__(PTHR, 1) k_prop(const float* __restrict__ temp,
                                                  const float* __restrict__ bfc,
                                                  float* __restrict__ out,
                                                  int N, int K)
{
    extern __shared__ __align__(16) unsigned char smem_raw[];
    __half*  sm   = reinterpret_cast<__half*>(smem_raw);
    uint32_t smb;
    asm("{ .reg .u64 t; cvta.to.shared.u64 t, %1; cvt.u32.u64 %0, t; }"
        : "=r"(smb) : "l"(smem_raw));
    const uint32_t mbar = smb + SMEMB;

    const int tid    = threadIdx.x;
    const int nwarps = gridDim.x * (PTHR / 32);
    const int gw     = blockIdx.x * (PTHR / 32) + (tid >> 5);
    const int lane   = tid & 31;

    if (tid == 0)
        asm volatile("mbarrier.init.shared.b64 [%0], 1;" :: "r"(mbar) : "memory");
    __syncthreads();

    // each warp owns a contiguous chunk of <=32 nodes; lane -> node (registers)
    const int npw    = (N + nwarps - 1) / nwarps;
    const int nodeLo = gw * npw;
    const int nodeHi = (nodeLo + npw < N) ? (nodeLo + npw) : N;
    const int cnt    = (nodeHi > nodeLo) ? (nodeHi - nodeLo) : 0;
    const int idx    = nodeLo + lane;
    const bool act   = (lane < cnt);

    int   myStart = act ? __ldg(&g_off[idx])     : 0;
    int   myNext  = act ? __ldg(&g_off[idx + 1]) : 0;
    float myDinv  = act ? g_dinv[idx]            : 0.0f;
    float myHid   = act ? g_hidden[idx]          : 0.0f;
    float mySelf  = act ? g_curwA[idx]           : 0.0f;

    unsigned target = 0;

    for (int k = 1; k <= K; k++) {
        const float gamma = __ldg(&temp[k]);
        const bool  last  = (k == K);
        const void* srcG  = (k & 1) ? (const void*)g_hA : (const void*)g_hB;
        __half*     dstH  = (k & 1) ? g_hB : g_hA;
        const unsigned ph = (unsigned)((k - 1) & 1);

        // ONE bulk TMA fill of the whole fp16 curw array
        if (tid == 0) {
            asm volatile("mbarrier.arrive.expect_tx.shared.b64 _, [%0], %1;"
                         :: "r"(mbar), "r"((unsigned)SMEMB) : "memory");
            asm volatile("cp.async.bulk.shared::cluster.global.mbarrier::complete_tx::bytes "
                         "[%0], [%1], %2, [%3];"
                         :: "r"(smb), "l"(srcG), "r"((unsigned)SMEMB), "r"(mbar) : "memory");
        }
        {   // all threads wait for fill completion (parity ph)
            unsigned done;
            asm volatile("{\n\t.reg .pred p;\n\t"
                         "mbarrier.try_wait.parity.shared.b64 p, [%1], %2;\n\t"
                         "selp.b32 %0, 1, 0, p;\n\t}"
                         : "=r"(done) : "r"(mbar), "r"(ph) : "memory");
            while (!done) {
                __nanosleep(32);
                asm volatile("{\n\t.reg .pred p;\n\t"
                             "mbarrier.try_wait.parity.shared.b64 p, [%1], %2;\n\t"
                             "selp.b32 %0, 1, 0, p;\n\t}"
                             : "=r"(done) : "r"(mbar), "r"(ph) : "memory");
            }
        }
        __syncthreads();

        // paired full-width smem gathers
        float mySum = 0.0f;
        for (int j = 0; j < cnt; j += 2) {
            int s0 = __shfl_sync(0xFFFFFFFFu, myStart, j);
            int e0 = __shfl_sync(0xFFFFFFFFu, myNext,  j);
            int j1 = (j + 1 < cnt) ? (j + 1) : j;
            int s1 = __shfl_sync(0xFFFFFFFFu, myStart, j1);
            int e1 = __shfl_sync(0xFFFFFFFFu, myNext,  j1);
            if (j + 1 >= cnt) { s1 = 0; e1 = 0; }

            float sum0 = 0.0f, sum1 = 0.0f;
            int   t0 = s0 + lane, t1 = s1 + lane;
            while (t0 < e0 || t1 < e1) {
                float v0 = 0.0f, v1 = 0.0f;
                if (t0 < e0) v0 = __half2float(sm[__ldg(&g_srow[t0])]);
                if (t1 < e1) v1 = __half2float(sm[__ldg(&g_srow[t1])]);
                sum0 += v0; sum1 += v1;
                t0 += 32;  t1 += 32;
            }
#pragma unroll
            for (int d = 16; d > 0; d >>= 1) {
                sum0 += __shfl_xor_sync(0xFFFFFFFFu, sum0, d);
                sum1 += __shfl_xor_sync(0xFFFFFFFFu, sum1, d);
            }
            if (lane == j)     mySum = sum0;
            if (lane == j + 1) mySum = sum1;
        }

        float cur = myDinv * (mySelf + mySum);
        myHid  = fmaf(gamma, cur, myHid);
        mySelf = myDinv * cur;

        if (!last) {
            if (act) dstH[idx] = __float2half(mySelf);   // coalesced 2B
            // grid barrier; gpu-scope fences emit CCTL.IVALL -> coherent
            __syncthreads();
            if (tid == 0) {
                __threadfence();                          // release (+IVALL)
                atomicAdd(&g_barrier, 1u);
                target += gridDim.x;
                while (*(volatile unsigned*)&g_barrier < target)
                    __nanosleep(32);
                __threadfence();                          // acquire (+IVALL)
            }
            __syncthreads();
        }
    }

    if (act) out[idx] = myHid + __ldg(&bfc[0]);
}

// ---------------------------------------------------------------------------
extern "C" void kernel_launch(void* const* d_in, const int* in_sizes, int n_in,
                              void* d_out, int out_size)
{
    const float* x    = (const float*)d_in[0];
    const int*   ei   = (const int*)  d_in[1];
    const float* W1   = (const float*)d_in[2];
    const float* b1   = (const float*)d_in[3];
    const float* W2   = (const float*)d_in[4];
    const float* b2   = (const float*)d_in[5];
    const float* temp = (const float*)d_in[6];
    const float* Wfc  = (const float*)d_in[7];
    const float* bfc  = (const float*)d_in[8];
    float*       out  = (float*)d_out;

    int N = in_sizes[0];
    int E = in_sizes[1] / 2;
    int K = in_sizes[6] - 1;

    const int* row = ei;
    const int* col = ei + E;

    int nb    = (N + NBLK - 1) / NBLK;
    int nscan = (N + SCANB - 1) / SCANB;   // 98 for N=100k (<128: lookback safe)

    bool vec_ok = (E % 4 == 0);
    int  E4 = E >> 2, rem = E & 3;
    int  eb_vec = (E4 + rem + EBLK - 1) / EBLK;
    int  eb_sca = (E + EBLK - 1) / EBLK;

    int dev = 0, sms = 0;
    cudaGetDevice(&dev);
    cudaDeviceGetAttribute(&sms, cudaDevAttrMultiProcessorCount, dev);
    if (sms <= 0) sms = 148;

    static int attr_done = 0;
    if (!attr_done) {
        cudaFuncSetAttribute(k_prop, cudaFuncAttributeMaxDynamicSharedMemorySize, SMEMT);
        attr_done = 1;
    }

    if (vec_ok) {
        k_mlp_hist<<<nb + eb_vec, NBLK>>>(x, W1, b1, W2, b2, Wfc, col, N, nb, E4, rem);
    } else {
        k_mlp_hist<<<nb + eb_sca, NBLK>>>(x, W1, b1, W2, b2, Wfc, col, N, nb, 0, E);
    }
    k_scan<<<nscan, SCANB>>>(temp, N, E);
    if (vec_ok) k_scatter_vec<<<eb_vec, EBLK>>>(row, col, E4, rem);
    else        k_scatter_sca<<<eb_sca, EBLK>>>(row, col, E);

    k_prop<<<sms, PTHR, SMEMT>>>(temp, bfc, out, N, K);
}